// round 7
// baseline (speedup 1.0000x reference)
#include <cuda_runtime.h>
#include <math.h>

#define BB 32
#define CC 256
#define HH 96
#define WW 96
#define CR 64

// Scratch (no allocs allowed)
__device__ float g_pooled[BB*9*CC];     // [b][p][c]  (block sums)
__device__ float g_hidden[BB*10*CR];    // [b][p][o]  (post-GELU)
__device__ float g_w1t[CC*CR];          // [k][o], BN inv folded
__device__ float g_bnb[CR];             // beta - mean*inv
__device__ unsigned g_cnt[BB];          // per-sample completion counters
                                        // (parity trick: &255, never reset)

// ---------------------------------------------------------------------------
// Kernel 1: pooling + prep + (last-block-per-sample) GEMM1+BN+GELU.
// 8192 blocks of 288 threads. Blocks 0..56 also do prep (w1T fold).
// The 256th finisher for each sample b computes g_hidden[b] while the rest
// of the grid keeps streaming — GEMM1 is hidden under pool's DRAM time.
// ---------------------------------------------------------------------------
__global__ void pool_kernel(const float* __restrict__ x,
                            const float* __restrict__ w1,
                            const float* __restrict__ bn_gamma,
                            const float* __restrict__ bn_beta,
                            const float* __restrict__ bn_mean,
                            const float* __restrict__ bn_var) {
    __shared__ float sv[10*CC];
    __shared__ unsigned s_ret;
    int bc = blockIdx.x;
    int t = threadIdx.x;

    // prep: 57*288 = 16416 >= 16384 items
    if (bc < 57) {
        int idx = bc * 288 + t;
        if (idx < CC*CR) {
            int k = idx >> 6, o = idx & 63;
            float inv = bn_gamma[o] * rsqrtf(bn_var[o] + 1e-5f);
            g_w1t[idx] = w1[o * CC + k] * inv;
        }
        if (idx < CR) {
            float inv = bn_gamma[idx] * rsqrtf(bn_var[idx] + 1e-5f);
            g_bnb[idx] = bn_beta[idx] - bn_mean[idx] * inv;
        }
    }

    // pooling: 9 warps, one 32x32 cell each
    int w = t >> 5;
    int lane = t & 31;
    int cy = w / 3, cx = w % 3;
    const float* base = x + (size_t)bc * (HH*WW) + cy * 32 * WW + cx * 32;
    float s = 0.f;
#pragma unroll
    for (int i = 0; i < 8; i++) {
        int f = lane + i * 32;
        int row = f >> 3, c4 = f & 7;
        float4 v = __ldcs(reinterpret_cast<const float4*>(base + row * WW + c4 * 4));
        s += v.x + v.y + v.z + v.w;
    }
#pragma unroll
    for (int o = 16; o; o >>= 1) s += __shfl_xor_sync(0xffffffffu, s, o);
    int b = bc >> 8, c = bc & 255;
    if (lane == 0)
        g_pooled[(b * 9 + w) * CC + c] = s;
    __syncthreads();

    if (t == 0) {
        __threadfence();
        s_ret = atomicAdd(&g_cnt[b], 1u);
    }
    __syncthreads();
    if ((s_ret & 255u) != 255u) return;

    // ---- last block for sample b: GEMM1 + BN + exact GELU ----
    if (t < CC) {
        float raw, sum = 0.f;
#pragma unroll
        for (int p = 0; p < 9; p++) {
            raw = g_pooled[(b * 9 + p) * CC + t];
            sum += raw;
            sv[p * CC + t] = raw * (1.0f / 1024.0f);
        }
        sv[9 * CC + t] = sum * (1.0f / (HH * WW));
    }
    __syncthreads();

#pragma unroll
    for (int i = 0; i < 3; i++) {
        int item = t + i * 288;
        if (item < 640) {
            int p = item >> 6, o = item & 63;
            const float* v = sv + p * CC;
            float acc = 0.f;
#pragma unroll 8
            for (int k = 0; k < CC; k++) acc = fmaf(g_w1t[k * CR + o], v[k], acc);
            float h = acc + g_bnb[o];
            h = 0.5f * h * (1.0f + erff(h * 0.70710678118654752f));
            g_hidden[(b * 10 + p) * CR + o] = h;
        }
    }
}

// ---------------------------------------------------------------------------
// Kernel 2: depthwise 3x3 conv + embedded GEMM2/softmax/mix prologue.
// The prologue (20 threads x 64 FMA) runs between cp.async commit and wait,
// fully hidden under the 36KB staging DMA.
// ---------------------------------------------------------------------------
#define PITCH 104
__global__ __launch_bounds__(288, 5) void dwconv_kernel(const float* __restrict__ x,
                                                        const float* __restrict__ dyn_weight,
                                                        const float* __restrict__ dyn_bias,
                                                        const float* __restrict__ w2,
                                                        const float* __restrict__ b2,
                                                        float* __restrict__ y) {
    __shared__ float tile[98 * PITCH];
    __shared__ float sc[20];
    __shared__ float wsm[10];
    int bc = blockIdx.x;
    int t = threadIdx.x;
    const float* img = x + (size_t)bc * (HH*WW);
    float* outimg = y + (size_t)bc * (HH*WW);

    // halo zeroing
    float4 z4 = make_float4(0.f,0.f,0.f,0.f);
    if (t < 26) {
        *reinterpret_cast<float4*>(&tile[t * 4]) = z4;
    } else if (t < 52) {
        *reinterpret_cast<float4*>(&tile[97 * PITCH + (t - 26) * 4]) = z4;
    } else if (t < 148) {
        tile[(t - 51) * PITCH + 3] = 0.f;
    } else if (t < 244) {
        tile[(t - 147) * PITCH + 100] = 0.f;
    }

    // stage image: 2304 x 16B cp.async, 8 per thread
#pragma unroll
    for (int i = 0; i < 8; i++) {
        int idx = t + i * 288;
        int r = idx / 24, j = idx % 24;
        unsigned smem_addr = (unsigned)__cvta_generic_to_shared(
            &tile[(r + 1) * PITCH + 4 + j * 4]);
        const float* gptr = img + r * WW + j * 4;
        asm volatile("cp.async.cg.shared.global [%0], [%1], 16;\n"
                     :: "r"(smem_addr), "l"(gptr));
    }
    asm volatile("cp.async.commit_group;\n");

    int b = bc >> 8, c = bc & 255;

    // GEMM2 for this (b,c): 10 positions x 2 groups, hidden under staging
    if (t < 20) {
        int p = t >> 1, g = t & 1;
        int n = g * CC + c;
        float acc = b2[n];
        const float* w2r = w2 + (size_t)n * CR;
        const float* hr = g_hidden + (b * 10 + p) * CR;
#pragma unroll 8
        for (int k = 0; k < CR; k++) acc = fmaf(w2r[k], hr[k], acc);
        sc[t] = acc;
    }
    __syncthreads();

    // softmax over G + mix with banks -> wsm[0..8] weights, wsm[9] bias
    if (t < 10) {
        float a0 = sc[2 * t], a1 = sc[2 * t + 1];
        float m = fmaxf(a0, a1);
        float e0 = __expf(a0 - m), e1 = __expf(a1 - m);
        float r = 1.0f / (e0 + e1);
        float p0 = e0 * r, p1 = e1 * r;
        if (t < 9) {
            wsm[t] = p0 * dyn_weight[c * 9 + t] + p1 * dyn_weight[(CC + c) * 9 + t];
        } else {
            wsm[9] = p0 * dyn_bias[c] + p1 * dyn_bias[CC + c];
        }
    }

    asm volatile("cp.async.wait_group 0;\n");
    __syncthreads();

    float w0 = wsm[0], w1_ = wsm[1], w2_ = wsm[2];
    float w3 = wsm[3], w4  = wsm[4], w5  = wsm[5];
    float w6 = wsm[6], w7  = wsm[7], w8  = wsm[8];
    float bv = wsm[9];

    int tx = t % 24;
    int ty = t / 24;
    int x0 = tx * 4;
    int r0 = ty * 8;

    float4 aA = make_float4(0.f,0.f,0.f,0.f);
    float4 aB = make_float4(0.f,0.f,0.f,0.f);
    float4 aC = make_float4(0.f,0.f,0.f,0.f);

#pragma unroll
    for (int s = 0; s < 10; ++s) {
        const float* row = &tile[(r0 + s) * PITCH + 4 + x0];
        float4 v = *reinterpret_cast<const float4*>(row);
        float l = row[-1];
        float rr = row[4];
        float c0 = v.x, c1 = v.y, c2 = v.z, c3 = v.w;

        aA.x = fmaf(l,  w6, fmaf(c0, w7, fmaf(c1, w8, aA.x)));
        aA.y = fmaf(c0, w6, fmaf(c1, w7, fmaf(c2, w8, aA.y)));
        aA.z = fmaf(c1, w6, fmaf(c2, w7, fmaf(c3, w8, aA.z)));
        aA.w = fmaf(c2, w6, fmaf(c3, w7, fmaf(rr, w8, aA.w)));

        aB.x = fmaf(l,  w3, fmaf(c0, w4, fmaf(c1, w5, aB.x)));
        aB.y = fmaf(c0, w3, fmaf(c1, w4, fmaf(c2, w5, aB.y)));
        aB.z = fmaf(c1, w3, fmaf(c2, w4, fmaf(c3, w5, aB.z)));
        aB.w = fmaf(c2, w3, fmaf(c3, w4, fmaf(rr, w5, aB.w)));

        aC.x = fmaf(l,  w0, fmaf(c0, w1_, fmaf(c1, w2_, aC.x)));
        aC.y = fmaf(c0, w0, fmaf(c1, w1_, fmaf(c2, w2_, aC.y)));
        aC.z = fmaf(c1, w0, fmaf(c2, w1_, fmaf(c3, w2_, aC.z)));
        aC.w = fmaf(c2, w0, fmaf(c3, w1_, fmaf(rr, w2_, aC.w)));

        if (s >= 2) {
            int yo = r0 + s - 2;
            float4 o;
            o.x = aA.x + bv; o.y = aA.y + bv; o.z = aA.z + bv; o.w = aA.w + bv;
            __stcs(reinterpret_cast<float4*>(outimg + yo * WW + x0), o);
        }
        aA = aB; aB = aC;
        aC = make_float4(0.f,0.f,0.f,0.f);
    }
}

extern "C" void kernel_launch(void* const* d_in, const int* in_sizes, int n_in,
                              void* d_out, int out_size) {
    const float* x          = (const float*)d_in[0];
    const float* dyn_weight = (const float*)d_in[1];
    const float* dyn_bias   = (const float*)d_in[2];
    const float* w1         = (const float*)d_in[3];
    const float* bn_gamma   = (const float*)d_in[4];
    const float* bn_beta    = (const float*)d_in[5];
    const float* bn_mean    = (const float*)d_in[6];
    const float* bn_var     = (const float*)d_in[7];
    const float* w2         = (const float*)d_in[8];
    const float* b2         = (const float*)d_in[9];
    float* out = (float*)d_out;

    pool_kernel<<<BB*CC, 288>>>(x, w1, bn_gamma, bn_beta, bn_mean, bn_var);
    dwconv_kernel<<<BB*CC, 288>>>(x, dyn_weight, dyn_bias, w2, b2, out);
}

// round 8
// speedup vs baseline: 1.2290x; 1.2290x over previous
#include <cuda_runtime.h>
#include <math.h>

#define BB 32
#define CC 256
#define HH 96
#define WW 96
#define CR 64

// Scratch (no allocs allowed)
__device__ float g_pooled[BB*9*CC];     // [b][p][c]  (block sums)
__device__ float g_weight[BB*9*CC];     // [b][p][c]
__device__ float g_bias[BB*CC];
__device__ float g_w1t[CC*CR];          // [k][o], BN inv folded
__device__ float g_w2t[CR*2*CC];        // [k][n]
__device__ float g_bnb[CR];             // beta - mean*inv
__device__ float g_dwt[2*9*CC];         // [g][p][c]

// ---------------------------------------------------------------------------
// Kernel 1: per-(b,c) 3x3 block sums. Writes [b][p][c].
// Blocks 0..113 additionally perform prep (transpose + BN fold), hidden
// under the DRAM-bound pooling pass.
// ---------------------------------------------------------------------------
__global__ void pool_kernel(const float* __restrict__ x,
                            const float* __restrict__ w1,
                            const float* __restrict__ bn_gamma,
                            const float* __restrict__ bn_beta,
                            const float* __restrict__ bn_mean,
                            const float* __restrict__ bn_var,
                            const float* __restrict__ w2,
                            const float* __restrict__ dyn_weight) {
    int bc = blockIdx.x;

    if (bc < 114) {
        int idx = bc * 288 + threadIdx.x;
        if (idx < CC*CR) {
            int k = idx >> 6, o = idx & 63;
            float inv = bn_gamma[o] * rsqrtf(bn_var[o] + 1e-5f);
            g_w1t[idx] = w1[o * CC + k] * inv;
        }
        if (idx < CR*2*CC) {
            int k = idx >> 9, n = idx & 511;
            g_w2t[idx] = w2[n * CR + k];
        }
        if (idx < 2*9*CC) {
            int g = idx / (9*CC);
            int rem = idx - g * 9 * CC;
            int p = rem >> 8, c = rem & 255;
            g_dwt[idx] = dyn_weight[(g * CC + c) * 9 + p];
        }
        if (idx < CR) {
            float inv = bn_gamma[idx] * rsqrtf(bn_var[idx] + 1e-5f);
            g_bnb[idx] = bn_beta[idx] - bn_mean[idx] * inv;
        }
    }

    int w = threadIdx.x >> 5;
    int lane = threadIdx.x & 31;
    int cy = w / 3, cx = w % 3;
    const float* base = x + (size_t)bc * (HH*WW) + cy * 32 * WW + cx * 32;
    float s = 0.f;
#pragma unroll
    for (int i = 0; i < 8; i++) {
        int f = lane + i * 32;
        int row = f >> 3, c4 = f & 7;
        float4 v = __ldcs(reinterpret_cast<const float4*>(base + row * WW + c4 * 4));
        s += v.x + v.y + v.z + v.w;
    }
#pragma unroll
    for (int o = 16; o; o >>= 1) s += __shfl_xor_sync(0xffffffffu, s, o);
    if (lane == 0)
        g_pooled[((bc >> 8) * 9 + w) * CC + (bc & 255)] = s;
}

// ---------------------------------------------------------------------------
// Kernel 2: fused proj. Grid (5, B) = 160 blocks; block handles positions
// p and p+5 of sample b.
// ---------------------------------------------------------------------------
__global__ __launch_bounds__(256) void projf_kernel(const float* __restrict__ dyn_bias,
                                                    const float* __restrict__ b2) {
    __shared__ float sv0[CC], sv1[CC];
    __shared__ float pa[2*256];
    __shared__ float sh0[CR], sh1[CR];
    int p = blockIdx.x;                   // 0..4
    int p2 = p + 5;                       // 5..9
    int b = blockIdx.y;
    int t = threadIdx.x;

    float v0 = g_pooled[(b * 9 + p) * CC + t] * (1.0f / 1024.0f);
    float v1;
    if (p2 < 9) {
        v1 = g_pooled[(b * 9 + p2) * CC + t] * (1.0f / 1024.0f);
    } else {
        float s = 0.f;
#pragma unroll
        for (int q = 0; q < 9; q++) s += g_pooled[(b * 9 + q) * CC + t];
        v1 = s * (1.0f / (HH * WW));
    }
    sv0[t] = v0; sv1[t] = v1;
    __syncthreads();

    int o = t & 63, slice = t >> 6;
    const float* w1s = g_w1t + slice * 64 * CR + o;
    const float* a0p = sv0 + slice * 64;
    const float* a1p = sv1 + slice * 64;
    float acc0 = 0.f, acc1 = 0.f;
#pragma unroll 8
    for (int k = 0; k < 64; k++) {
        float w = w1s[k * CR];
        acc0 = fmaf(w, a0p[k], acc0);
        acc1 = fmaf(w, a1p[k], acc1);
    }
    pa[t] = acc0; pa[256 + t] = acc1;
    __syncthreads();

    if (t < 128) {
        int pos = t >> 6, oo = t & 63;
        const float* pp = pa + pos * 256;
        float h = pp[oo] + pp[oo + 64] + pp[oo + 128] + pp[oo + 192] + g_bnb[oo];
        h = 0.5f * h * (1.0f + erff(h * 0.70710678118654752f));
        if (pos) sh1[oo] = h; else sh0[oo] = h;
    }
    __syncthreads();

    int c = t;
    float a0 = b2[c], a1 = b2[CC + c];
    float d0 = a0, d1 = a1;
#pragma unroll 8
    for (int k = 0; k < CR; k++) {
        float w_0 = g_w2t[k * 512 + c];
        float w_1 = g_w2t[k * 512 + CC + c];
        float h0 = sh0[k], h1 = sh1[k];
        a0 = fmaf(w_0, h0, a0); a1 = fmaf(w_1, h0, a1);
        d0 = fmaf(w_0, h1, d0); d1 = fmaf(w_1, h1, d1);
    }
    {
        float m = fmaxf(a0, a1);
        float e0 = __expf(a0 - m), e1 = __expf(a1 - m);
        float r = 1.0f / (e0 + e1);
        g_weight[(b * 9 + p) * CC + c] = e0 * r * g_dwt[p * CC + c]
                                       + e1 * r * g_dwt[(9 + p) * CC + c];
    }
    {
        float m = fmaxf(d0, d1);
        float e0 = __expf(d0 - m), e1 = __expf(d1 - m);
        float r = 1.0f / (e0 + e1);
        if (p2 < 9) {
            g_weight[(b * 9 + p2) * CC + c] = e0 * r * g_dwt[p2 * CC + c]
                                            + e1 * r * g_dwt[(9 + p2) * CC + c];
        } else {
            g_bias[b * CC + c] = e0 * r * dyn_bias[c] + e1 * r * dyn_bias[CC + c];
        }
    }
}

// ---------------------------------------------------------------------------
// Kernel 3: depthwise 3x3 conv + bias. PITCH=96 (no halo columns in smem;
// column edges handled by predicated selects) -> 36.75KB tile -> 6 blocks/SM.
// Staging via cp.async.cg.
// ---------------------------------------------------------------------------
#define PITCH 96
__global__ __launch_bounds__(288, 6) void dwconv_kernel(const float* __restrict__ x,
                                                        float* __restrict__ y) {
    __shared__ float tile[98 * PITCH];
    int bc = blockIdx.x;
    int t = threadIdx.x;
    const float* img = x + (size_t)bc * (HH*WW);
    float* outimg = y + (size_t)bc * (HH*WW);

    // zero halo rows 0 and 97 (24 float4 each)
    float4 z4 = make_float4(0.f,0.f,0.f,0.f);
    if (t < 24) {
        *reinterpret_cast<float4*>(&tile[t * 4]) = z4;
    } else if (t < 48) {
        *reinterpret_cast<float4*>(&tile[97 * PITCH + (t - 24) * 4]) = z4;
    }

    // stage image: 2304 x 16B cp.async, 8 per thread
#pragma unroll
    for (int i = 0; i < 8; i++) {
        int idx = t + i * 288;
        int r = idx / 24, j = idx % 24;
        unsigned smem_addr = (unsigned)__cvta_generic_to_shared(
            &tile[(r + 1) * PITCH + j * 4]);
        const float* gptr = img + r * WW + j * 4;
        asm volatile("cp.async.cg.shared.global [%0], [%1], 16;\n"
                     :: "r"(smem_addr), "l"(gptr));
    }
    asm volatile("cp.async.commit_group;\n");
    asm volatile("cp.async.wait_group 0;\n");
    __syncthreads();

    int b = bc >> 8, c = bc & 255;
    float w0 = g_weight[(b*9+0)*CC+c], w1_ = g_weight[(b*9+1)*CC+c], w2_ = g_weight[(b*9+2)*CC+c];
    float w3 = g_weight[(b*9+3)*CC+c], w4  = g_weight[(b*9+4)*CC+c], w5  = g_weight[(b*9+5)*CC+c];
    float w6 = g_weight[(b*9+6)*CC+c], w7  = g_weight[(b*9+7)*CC+c], w8  = g_weight[(b*9+8)*CC+c];
    float bv = g_bias[bc];

    int tx = t % 24;
    int ty = t / 24;
    int x0 = tx * 4;
    int r0 = ty * 8;
    bool hasL = (tx > 0), hasR = (tx < 23);

    float4 aA = make_float4(0.f,0.f,0.f,0.f);
    float4 aB = make_float4(0.f,0.f,0.f,0.f);
    float4 aC = make_float4(0.f,0.f,0.f,0.f);

#pragma unroll
    for (int s = 0; s < 10; ++s) {
        const float* row = &tile[(r0 + s) * PITCH + x0];
        float4 v = *reinterpret_cast<const float4*>(row);
        float l  = hasL ? row[-1] : 0.f;
        float rr = hasR ? row[4]  : 0.f;
        float c0 = v.x, c1 = v.y, c2 = v.z, c3 = v.w;

        aA.x = fmaf(l,  w6, fmaf(c0, w7, fmaf(c1, w8, aA.x)));
        aA.y = fmaf(c0, w6, fmaf(c1, w7, fmaf(c2, w8, aA.y)));
        aA.z = fmaf(c1, w6, fmaf(c2, w7, fmaf(c3, w8, aA.z)));
        aA.w = fmaf(c2, w6, fmaf(c3, w7, fmaf(rr, w8, aA.w)));

        aB.x = fmaf(l,  w3, fmaf(c0, w4, fmaf(c1, w5, aB.x)));
        aB.y = fmaf(c0, w3, fmaf(c1, w4, fmaf(c2, w5, aB.y)));
        aB.z = fmaf(c1, w3, fmaf(c2, w4, fmaf(c3, w5, aB.z)));
        aB.w = fmaf(c2, w3, fmaf(c3, w4, fmaf(rr, w5, aB.w)));

        aC.x = fmaf(l,  w0, fmaf(c0, w1_, fmaf(c1, w2_, aC.x)));
        aC.y = fmaf(c0, w0, fmaf(c1, w1_, fmaf(c2, w2_, aC.y)));
        aC.z = fmaf(c1, w0, fmaf(c2, w1_, fmaf(c3, w2_, aC.z)));
        aC.w = fmaf(c2, w0, fmaf(c3, w1_, fmaf(rr, w2_, aC.w)));

        if (s >= 2) {
            int yo = r0 + s - 2;
            float4 o;
            o.x = aA.x + bv; o.y = aA.y + bv; o.z = aA.z + bv; o.w = aA.w + bv;
            __stcs(reinterpret_cast<float4*>(outimg + yo * WW + x0), o);
        }
        aA = aB; aB = aC;
        aC = make_float4(0.f,0.f,0.f,0.f);
    }
}

extern "C" void kernel_launch(void* const* d_in, const int* in_sizes, int n_in,
                              void* d_out, int out_size) {
    const float* x          = (const float*)d_in[0];
    const float* dyn_weight = (const float*)d_in[1];
    const float* dyn_bias   = (const float*)d_in[2];
    const float* w1         = (const float*)d_in[3];
    const float* bn_gamma   = (const float*)d_in[4];
    const float* bn_beta    = (const float*)d_in[5];
    const float* bn_mean    = (const float*)d_in[6];
    const float* bn_var     = (const float*)d_in[7];
    const float* w2         = (const float*)d_in[8];
    const float* b2         = (const float*)d_in[9];
    float* out = (float*)d_out;

    pool_kernel<<<BB*CC, 288>>>(x, w1, bn_gamma, bn_beta, bn_mean, bn_var, w2, dyn_weight);
    dim3 pg(5, BB);
    projf_kernel<<<pg, 256>>>(dyn_bias, b2);
    dwconv_kernel<<<BB*CC, 288>>>(x, out);
}